// round 12
// baseline (speedup 1.0000x reference)
#include <cuda_runtime.h>
#include <cuda_bf16.h>
#include <cstdint>
#include <math.h>

#define Bn 128
#define Ln 400
#define Dn 1024
#define Cn 256

// Activation ping-pong planes (bf16 hi/lo), layout [L, B, C]
__device__ __nv_bfloat16 g_Ahi[(size_t)Bn * Ln * Cn];
__device__ __nv_bfloat16 g_Alo[(size_t)Bn * Ln * Cn];
__device__ __nv_bfloat16 g_Bhi[(size_t)Bn * Ln * Cn];
__device__ __nv_bfloat16 g_Blo[(size_t)Bn * Ln * Cn];
// Split embeddings [B*L, D]
__device__ __nv_bfloat16 g_Ehi[(size_t)Bn * Ln * Dn];
__device__ __nv_bfloat16 g_Elo[(size_t)Bn * Ln * Dn];
// Split weights: conv [layer][tap][o][i], proj [o][k]
__device__ __nv_bfloat16 g_wkhi[3 * 3 * Cn * Cn];
__device__ __nv_bfloat16 g_wklo[3 * 3 * Cn * Cn];
__device__ __nv_bfloat16 g_wlhi[(size_t)Cn * Dn];
__device__ __nv_bfloat16 g_wllo[(size_t)Cn * Dn];

// Row stride 80 B (40 bf16): ldmatrix 8-row phases hit banks r*20 mod 32
// (all distinct), 16B-aligned for cp.async.
#define RSTR 80
#define PLA (128 * RSTR)             // A plane: 10240 B
#define PLB (256 * RSTR)             // B plane: 20480 B
#define STAGE (2 * PLA + 2 * PLB)    // 61440 B
#define NSTG 3
#define SMEM_TOT (NSTG * STAGE)      // 184320 B -> 1 CTA/SM, 16 warps

// ---------------- helpers ----------------
__device__ __forceinline__ uint32_t s2u(const void* p) {
    uint32_t a;
    asm("{ .reg .u64 t; cvta.to.shared.u64 t, %1; cvt.u32.u64 %0, t; }" : "=r"(a) : "l"(p));
    return a;
}
__device__ __forceinline__ void cpa16(uint32_t dst, const void* src) {
    asm volatile("cp.async.cg.shared.global [%0], [%1], 16;" :: "r"(dst), "l"(src) : "memory");
}
__device__ __forceinline__ void zfill16(uint32_t dst) {
    asm volatile("st.shared.v4.u32 [%0], {%1,%1,%1,%1};" :: "r"(dst), "r"(0u) : "memory");
}
__device__ __forceinline__ void cpa_commit() {
    asm volatile("cp.async.commit_group;" ::: "memory");
}
template <int N>
__device__ __forceinline__ void cpa_wait() {
    asm volatile("cp.async.wait_group %0;" :: "n"(N) : "memory");
}
__device__ __forceinline__ void ldsm4(uint32_t* r, uint32_t a) {
    asm volatile("ldmatrix.sync.aligned.m8n8.x4.shared.b16 {%0,%1,%2,%3}, [%4];"
                 : "=r"(r[0]), "=r"(r[1]), "=r"(r[2]), "=r"(r[3]) : "r"(a));
}
__device__ __forceinline__ void mma16(float* d, const uint32_t* a, uint32_t b0, uint32_t b1) {
    asm volatile(
        "mma.sync.aligned.m16n8k16.row.col.f32.bf16.bf16.f32 "
        "{%0,%1,%2,%3}, {%4,%5,%6,%7}, {%8,%9}, {%0,%1,%2,%3};"
        : "+f"(d[0]), "+f"(d[1]), "+f"(d[2]), "+f"(d[3])
        : "r"(a[0]), "r"(a[1]), "r"(a[2]), "r"(a[3]), "r"(b0), "r"(b1));
}
__device__ __forceinline__ void split2(float v0, float v1,
                                       __nv_bfloat162* hi, __nv_bfloat162* lo) {
    __nv_bfloat162 h, l;
    h.x = __float2bfloat16(v0);
    h.y = __float2bfloat16(v1);
    l.x = __float2bfloat16(v0 - __bfloat162float(h.x));
    l.y = __float2bfloat16(v1 - __bfloat162float(h.y));
    *hi = h; *lo = l;
}

// ---------------------------------------------------------------------------
// Prep: all weights in ONE kernel.
// conv: w[o][i][k] -> [(tap*256+o)*256 + i];  proj: Wl[k][o] -> [o*1024+k]
// ---------------------------------------------------------------------------
__global__ void wprep_all_kernel(const float* __restrict__ w0,
                                 const float* __restrict__ w1,
                                 const float* __restrict__ w2,
                                 const float* __restrict__ wl,
                                 __nv_bfloat16* __restrict__ wkh,
                                 __nv_bfloat16* __restrict__ wkl,
                                 __nv_bfloat16* __restrict__ wlh,
                                 __nv_bfloat16* __restrict__ wll) {
    const int bid = blockIdx.x;
    if (bid < 2304) {
        const int layer = bid / 768, blk = bid - layer * 768;
        const float* w = (layer == 0) ? w0 : (layer == 1) ? w1 : w2;
        const int idx = blk * 256 + threadIdx.x;            // 0..196607
        const int o = idx / (Cn * 3);
        const int rem = idx - o * (Cn * 3);
        const int i = rem / 3, k = rem - i * 3;
        const float v = w[idx];
        const __nv_bfloat16 h = __float2bfloat16(v);
        const size_t d = (size_t)layer * 3 * Cn * Cn + ((size_t)k * Cn + o) * Cn + i;
        wkh[d] = h;
        wkl[d] = __float2bfloat16(v - __bfloat162float(h));
    } else {
        const int idx = (bid - 2304) * 256 + threadIdx.x;   // 0..262143
        const int o = idx >> 10, k = idx & 1023;
        const float v = wl[(size_t)k * Cn + o];
        const __nv_bfloat16 h = __float2bfloat16(v);
        wlh[idx] = h;
        wll[idx] = __float2bfloat16(v - __bfloat162float(h));
    }
}
__global__ void esplit_kernel(const float4* __restrict__ E,
                              __nv_bfloat162* __restrict__ hi,
                              __nv_bfloat162* __restrict__ lo) {
    size_t idx = (size_t)blockIdx.x * 256 + threadIdx.x;
    float4 v = E[idx];
    split2(v.x, v.y, &hi[idx * 2], &lo[idx * 2]);
    split2(v.z, v.w, &hi[idx * 2 + 1], &lo[idx * 2 + 1]);
}

// ---------------------------------------------------------------------------
// bf16x3 mma GEMM/conv on [L,B,C]. M128 x N256 per CTA, 512 threads, 16 warps
// (wm=(wid&3)*32, wn=(wid>>2)*64). 3-stage cp.async pipeline, 2 groups in
// flight (wait_group 1): iteration c = wait(c) -> sync -> load(c+2) -> compute(c).
// Conv: 24 k-chunks (3 taps x 8), A tile loaded once per l. Proj: 32 chunks.
// ---------------------------------------------------------------------------
template <bool PROJ, int DIL, bool RELU, bool SPLIT>
__global__ void __launch_bounds__(512, 1) mma_kernel(
    const __nv_bfloat16* __restrict__ Xhi, const __nv_bfloat16* __restrict__ Xlo,
    const __nv_bfloat16* __restrict__ Whi, const __nv_bfloat16* __restrict__ Wlo,
    const float* __restrict__ bias,
    __nv_bfloat16* __restrict__ Yhi, __nv_bfloat16* __restrict__ Ylo,
    float* __restrict__ Yf) {
    constexpr int NCH = PROJ ? 32 : 24;

    extern __shared__ __align__(16) char smem[];
    const int tid = threadIdx.x, wid = tid >> 5, lane = tid & 31;
    const int r4 = lane >> 2, c4 = lane & 3;
    const int wm = (wid & 3) * 32, wn = (wid >> 2) * 64;
    const uint32_t smem_u = s2u(smem);

    // ldmatrix per-lane address components
    const int lane15 = lane & 15;
    const uint32_t a_off = ((lane >> 4) & 1) << 4;
    const int b_rowl = (lane & 7) + ((lane >> 4) & 1) * 8;
    const uint32_t b_off = ((lane >> 3) & 1) << 4;

    const int tile = blockIdx.x;           // proj: m-tile; conv: l index
    const int m0 = tile * 128;

    float acc[2][8][4];
#pragma unroll
    for (int mt = 0; mt < 2; mt++)
#pragma unroll
        for (int nt = 0; nt < 8; nt++)
#pragma unroll
            for (int j = 0; j < 4; j++) acc[mt][nt][j] = 0.f;

    auto load_chunk = [&](int c) {
        const uint32_t sb = smem_u + (c % NSTG) * STAGE;
        const int tap = PROJ ? 0 : (c >> 3);
        const int kc = PROJ ? c : (c & 7);
        const int lsrc = PROJ ? 0 : (tile + (tap - 1) * DIL);
        const bool avalid = PROJ || ((unsigned)lsrc < (unsigned)Ln);
#pragma unroll
        for (int q = 0; q < 2; q++) {                       // A: 1024 ops
            const int idx = q * 512 + tid;
            const int plane = idx >> 9, row = (idx >> 2) & 127, cg = idx & 3;
            const uint32_t dst = sb + plane * PLA + row * RSTR + cg * 16;
            const __nv_bfloat16* P = plane ? Xlo : Xhi;
            if (PROJ)
                cpa16(dst, P + (size_t)(m0 + row) * Dn + kc * 32 + cg * 8);
            else if (avalid)
                cpa16(dst, P + ((size_t)lsrc * Bn + row) * Cn + kc * 32 + cg * 8);
            else
                zfill16(dst);
        }
#pragma unroll
        for (int q = 0; q < 4; q++) {                       // B: 2048 ops (256 rows)
            const int idx = q * 512 + tid;
            const int plane = idx >> 10, row = (idx >> 2) & 255, cg = idx & 3;
            const uint32_t dst = sb + 2 * PLA + plane * PLB + row * RSTR + cg * 16;
            const __nv_bfloat16* P = plane ? Wlo : Whi;
            if (PROJ)
                cpa16(dst, P + (size_t)row * Dn + kc * 32 + cg * 8);
            else
                cpa16(dst, P + ((size_t)tap * Cn + row) * Cn + kc * 32 + cg * 8);
        }
        cpa_commit();
    };

    load_chunk(0);
    load_chunk(1);
    for (int c = 0; c < NCH; c++) {
        cpa_wait<1>();          // stage c resident (c+1 may still be in flight)
        __syncthreads();        // all threads past compute(c-1): stage (c+2)%3 free
        if (c + 2 < NCH) load_chunk(c + 2);

        const uint32_t sb = smem_u + (c % NSTG) * STAGE;
        const uint32_t ab = sb + (wm + lane15) * RSTR + a_off;
        const uint32_t bbs = sb + 2 * PLA + (wn + b_rowl) * RSTR + b_off;
#pragma unroll
        for (int ks = 0; ks < 2; ks++) {
            uint32_t ah[2][4], al[2][4];
            ldsm4(ah[0], ab + ks * 32);
            ldsm4(ah[1], ab + 16 * RSTR + ks * 32);
            ldsm4(al[0], ab + PLA + ks * 32);
            ldsm4(al[1], ab + PLA + 16 * RSTR + ks * 32);
            uint32_t bh[4][4], blr[4][4];
#pragma unroll
            for (int p = 0; p < 4; p++) {
                ldsm4(bh[p],  bbs + p * 16 * RSTR + ks * 32);
                ldsm4(blr[p], bbs + PLB + p * 16 * RSTR + ks * 32);
            }
#pragma unroll
            for (int p = 0; p < 4; p++) {
#pragma unroll
                for (int h = 0; h < 2; h++) {
                    const int nt = 2 * p + h;
                    const uint32_t b0h = bh[p][2 * h],  b1h = bh[p][2 * h + 1];
                    const uint32_t b0l = blr[p][2 * h], b1l = blr[p][2 * h + 1];
                    mma16(acc[0][nt], ah[0], b0h, b1h);
                    mma16(acc[1][nt], ah[1], b0h, b1h);
                    mma16(acc[0][nt], ah[0], b0l, b1l);
                    mma16(acc[1][nt], ah[1], b0l, b1l);
                    mma16(acc[0][nt], al[0], b0h, b1h);
                    mma16(acc[1][nt], al[1], b0h, b1h);
                }
            }
        }
    }

    // ---- epilogue: bias (+ReLU); split-store to [L,B,C] or fp32 [B,L,C] ----
#pragma unroll
    for (int mt = 0; mt < 2; mt++) {
        const int rowl = wm + mt * 16 + r4;    // local m row (conv: batch b)
#pragma unroll
        for (int half = 0; half < 2; half++) {
            const int rl = rowl + half * 8;
            size_t yrow;
            if (PROJ) {
                const int m = m0 + rl;
                const int b = m / Ln, l = m - b * Ln;
                yrow = (size_t)l * Bn + b;
            } else if (SPLIT) {
                yrow = (size_t)tile * Bn + rl;           // [L,B,C]
            } else {
                yrow = (size_t)rl * Ln + tile;           // fp32 out [B,L,C]
            }
#pragma unroll
            for (int nt = 0; nt < 8; nt++) {
                const int col = wn + nt * 8 + c4 * 2;
                const float bz0 = __ldg(bias + col);
                const float bz1 = __ldg(bias + col + 1);
                float v0 = acc[mt][nt][2 * half]     + bz0;
                float v1 = acc[mt][nt][2 * half + 1] + bz1;
                if (RELU) { v0 = fmaxf(v0, 0.f); v1 = fmaxf(v1, 0.f); }
                if (SPLIT) {
                    split2(v0, v1,
                           (__nv_bfloat162*)(Yhi + yrow * Cn + col),
                           (__nv_bfloat162*)(Ylo + yrow * Cn + col));
                } else {
                    *(float2*)(Yf + yrow * Cn + col) = make_float2(v0, v1);
                }
            }
        }
    }
}

// ---------------------------------------------------------------------------
// LayerNorm over L per (b,c) on split [L,B,C] planes, 2-pass, strip-parallel.
// Block 256 thr = 64 channels x 4 L-strips. Grid (Bn, 4).
// torch-style: unbiased var (ddof=1), divide by (std + eps).
// ---------------------------------------------------------------------------
template <bool RELU>
__global__ __launch_bounds__(256) void ln_kernel(
    __nv_bfloat16* __restrict__ hi, __nv_bfloat16* __restrict__ lo,
    const float* __restrict__ g, const float* __restrict__ be) {
    __shared__ float red[2][4][64];
    __shared__ float stat[2][64];
    const int b = blockIdx.x, cg = blockIdx.y;
    const int cl = threadIdx.x & 63, strip = threadIdx.x >> 6;
    const size_t base = (size_t)b * Cn + cg * 64 + cl;

    float s = 0.f, q = 0.f;
    for (int l = strip; l < Ln; l += 4) {
        const size_t off = base + (size_t)l * Bn * Cn;
        float x = __bfloat162float(hi[off]) + __bfloat162float(lo[off]);
        if (RELU) x = fmaxf(x, 0.f);
        s += x; q += x * x;
    }
    red[0][strip][cl] = s;
    red[1][strip][cl] = q;
    __syncthreads();
    if (threadIdx.x < 64) {
        float st = red[0][0][cl] + red[0][1][cl] + red[0][2][cl] + red[0][3][cl];
        float qt = red[1][0][cl] + red[1][1][cl] + red[1][2][cl] + red[1][3][cl];
        const float mean = st * (1.f / Ln);
        const float var = fmaxf((qt - st * mean) * (1.f / (Ln - 1)), 0.f);
        stat[0][cl] = mean;
        stat[1][cl] = 1.f / (sqrtf(var) + 1e-6f);
    }
    __syncthreads();
    const float mean = stat[0][cl], inv = stat[1][cl];
    for (int l = strip; l < Ln; l += 4) {
        const size_t off = base + (size_t)l * Bn * Cn;
        float x = __bfloat162float(hi[off]) + __bfloat162float(lo[off]);
        if (RELU) x = fmaxf(x, 0.f);
        const float y = g[l] * ((x - mean) * inv) + be[l];
        const __nv_bfloat16 h = __float2bfloat16(y);
        hi[off] = h;
        lo[off] = __float2bfloat16(y - __bfloat162float(h));
    }
}

// ---------------------------------------------------------------------------
// Host orchestration
// ---------------------------------------------------------------------------
extern "C" void kernel_launch(void* const* d_in, const int* in_sizes, int n_in,
                              void* d_out, int out_size) {
    const float* E   = (const float*)d_in[0];
    const float* Wl  = (const float*)d_in[2];
    const float* bl  = (const float*)d_in[3];
    const float* w0  = (const float*)d_in[4];
    const float* b0  = (const float*)d_in[5];
    const float* w1  = (const float*)d_in[6];
    const float* b1  = (const float*)d_in[7];
    const float* w2  = (const float*)d_in[8];
    const float* b2  = (const float*)d_in[9];
    const float* g1  = (const float*)d_in[10];
    const float* be1 = (const float*)d_in[11];
    const float* g2  = (const float*)d_in[12];
    const float* be2 = (const float*)d_in[13];
    float* out = (float*)d_out;

    __nv_bfloat16 *Ah, *Al, *Bh, *Bl, *Eh, *El, *wkh, *wkl, *wlh, *wll;
    cudaGetSymbolAddress((void**)&Ah, g_Ahi);
    cudaGetSymbolAddress((void**)&Al, g_Alo);
    cudaGetSymbolAddress((void**)&Bh, g_Bhi);
    cudaGetSymbolAddress((void**)&Bl, g_Blo);
    cudaGetSymbolAddress((void**)&Eh, g_Ehi);
    cudaGetSymbolAddress((void**)&El, g_Elo);
    cudaGetSymbolAddress((void**)&wkh, g_wkhi);
    cudaGetSymbolAddress((void**)&wkl, g_wklo);
    cudaGetSymbolAddress((void**)&wlh, g_wlhi);
    cudaGetSymbolAddress((void**)&wll, g_wllo);
    __nv_bfloat16* wk0h = wkh;               __nv_bfloat16* wk0l = wkl;
    __nv_bfloat16* wk1h = wkh + 3 * Cn * Cn; __nv_bfloat16* wk1l = wkl + 3 * Cn * Cn;
    __nv_bfloat16* wk2h = wkh + 6 * Cn * Cn; __nv_bfloat16* wk2l = wkl + 6 * Cn * Cn;

    cudaFuncSetAttribute(mma_kernel<true, 1, false, true>,
                         cudaFuncAttributeMaxDynamicSharedMemorySize, SMEM_TOT);
    cudaFuncSetAttribute(mma_kernel<false, 1, true, true>,
                         cudaFuncAttributeMaxDynamicSharedMemorySize, SMEM_TOT);
    cudaFuncSetAttribute(mma_kernel<false, 1, false, true>,
                         cudaFuncAttributeMaxDynamicSharedMemorySize, SMEM_TOT);
    cudaFuncSetAttribute(mma_kernel<false, 2, false, true>,
                         cudaFuncAttributeMaxDynamicSharedMemorySize, SMEM_TOT);
    cudaFuncSetAttribute(mma_kernel<false, 2, false, false>,
                         cudaFuncAttributeMaxDynamicSharedMemorySize, SMEM_TOT);

    wprep_all_kernel<<<3328, 256>>>(w0, w1, w2, Wl, wkh, wkl, wlh, wll);
    esplit_kernel<<<51200, 256>>>((const float4*)E, (__nv_bfloat162*)Eh,
                                  (__nv_bfloat162*)El);

    // projection: [51200,1024] x [1024,256] -> A planes [L,B,C]
    mma_kernel<true, 1, false, true><<<400, 512, SMEM_TOT>>>(
        Eh, El, wlh, wll, bl, Ah, Al, nullptr);

    const int CG = Ln;              // 400 l-tiles, full N per CTA
    const dim3 LG(Bn, 4);

    // net 1: A -> B
    mma_kernel<false, 1, true,  true><<<CG, 512, SMEM_TOT>>>(Ah, Al, wk0h, wk0l, b0, Bh, Bl, nullptr);
    ln_kernel<false><<<LG, 256>>>(Bh, Bl, g1, be1);
    mma_kernel<false, 1, false, true><<<CG, 512, SMEM_TOT>>>(Bh, Bl, wk1h, wk1l, b1, Ah, Al, nullptr);
    mma_kernel<false, 2, false, true><<<CG, 512, SMEM_TOT>>>(Ah, Al, wk2h, wk2l, b2, Bh, Bl, nullptr);

    ln_kernel<true><<<LG, 256>>>(Bh, Bl, g2, be2);   // ReLU + outer LN

    // net 2: B -> A
    mma_kernel<false, 1, true,  true><<<CG, 512, SMEM_TOT>>>(Bh, Bl, wk0h, wk0l, b0, Ah, Al, nullptr);
    ln_kernel<false><<<LG, 256>>>(Ah, Al, g1, be1);
    mma_kernel<false, 1, false, true><<<CG, 512, SMEM_TOT>>>(Ah, Al, wk1h, wk1l, b1, Bh, Bl, nullptr);
    mma_kernel<false, 2, false, true><<<CG, 512, SMEM_TOT>>>(Bh, Bl, wk2h, wk2l, b2, Ah, Al, nullptr);

    // net 3: A -> B
    mma_kernel<false, 1, true,  true><<<CG, 512, SMEM_TOT>>>(Ah, Al, wk0h, wk0l, b0, Bh, Bl, nullptr);
    ln_kernel<false><<<LG, 256>>>(Bh, Bl, g1, be1);
    mma_kernel<false, 1, false, true><<<CG, 512, SMEM_TOT>>>(Bh, Bl, wk1h, wk1l, b1, Ah, Al, nullptr);
    mma_kernel<false, 2, false, true><<<CG, 512, SMEM_TOT>>>(Ah, Al, wk2h, wk2l, b2, Bh, Bl, nullptr);

    // net 4: B -> out (final conv writes fp32 d_out [B,L,C])
    mma_kernel<false, 1, true,  true><<<CG, 512, SMEM_TOT>>>(Bh, Bl, wk0h, wk0l, b0, Ah, Al, nullptr);
    ln_kernel<false><<<LG, 256>>>(Ah, Al, g1, be1);
    mma_kernel<false, 1, false, true><<<CG, 512, SMEM_TOT>>>(Ah, Al, wk1h, wk1l, b1, Bh, Bl, nullptr);
    mma_kernel<false, 2, false, false><<<CG, 512, SMEM_TOT>>>(Bh, Bl, wk2h, wk2l, b2, nullptr, nullptr, out);
}

// round 13
// speedup vs baseline: 1.0006x; 1.0006x over previous
#include <cuda_runtime.h>
#include <cuda_bf16.h>
#include <cstdint>
#include <math.h>

#define Bn 128
#define Ln 400
#define Dn 1024
#define Cn 256

// Activation ping-pong planes (bf16 hi/lo), layout [L, B, C]
__device__ __nv_bfloat16 g_Ahi[(size_t)Bn * Ln * Cn];
__device__ __nv_bfloat16 g_Alo[(size_t)Bn * Ln * Cn];
__device__ __nv_bfloat16 g_Bhi[(size_t)Bn * Ln * Cn];
__device__ __nv_bfloat16 g_Blo[(size_t)Bn * Ln * Cn];
// Split embeddings [B*L, D]
__device__ __nv_bfloat16 g_Ehi[(size_t)Bn * Ln * Dn];
__device__ __nv_bfloat16 g_Elo[(size_t)Bn * Ln * Dn];
// Split weights: conv [layer][tap][o][i], proj [o][k]
__device__ __nv_bfloat16 g_wkhi[3 * 3 * Cn * Cn];
__device__ __nv_bfloat16 g_wklo[3 * 3 * Cn * Cn];
__device__ __nv_bfloat16 g_wlhi[(size_t)Cn * Dn];
__device__ __nv_bfloat16 g_wllo[(size_t)Cn * Dn];

// Row stride 80 B (40 bf16): ldmatrix 8-row phases hit banks r*20 mod 32
// (all distinct), 16B-aligned for cp.async.
#define RSTR 80
#define PLA (128 * RSTR)             // A plane: 10240 B
#define PLB (256 * RSTR)             // B plane: 20480 B
#define STAGE (2 * PLA + 2 * PLB)    // 61440 B
#define NSTG 3
#define SMEM_TOT (NSTG * STAGE)      // 184320 B -> 1 CTA/SM, 16 warps

// ---------------- helpers ----------------
__device__ __forceinline__ uint32_t s2u(const void* p) {
    uint32_t a;
    asm("{ .reg .u64 t; cvta.to.shared.u64 t, %1; cvt.u32.u64 %0, t; }" : "=r"(a) : "l"(p));
    return a;
}
__device__ __forceinline__ void cpa16(uint32_t dst, const void* src) {
    asm volatile("cp.async.cg.shared.global [%0], [%1], 16;" :: "r"(dst), "l"(src) : "memory");
}
__device__ __forceinline__ void zfill16(uint32_t dst) {
    asm volatile("st.shared.v4.u32 [%0], {%1,%1,%1,%1};" :: "r"(dst), "r"(0u) : "memory");
}
__device__ __forceinline__ void cpa_commit() {
    asm volatile("cp.async.commit_group;" ::: "memory");
}
template <int N>
__device__ __forceinline__ void cpa_wait() {
    asm volatile("cp.async.wait_group %0;" :: "n"(N) : "memory");
}
__device__ __forceinline__ void ldsm4(uint32_t* r, uint32_t a) {
    asm volatile("ldmatrix.sync.aligned.m8n8.x4.shared.b16 {%0,%1,%2,%3}, [%4];"
                 : "=r"(r[0]), "=r"(r[1]), "=r"(r[2]), "=r"(r[3]) : "r"(a));
}
__device__ __forceinline__ void mma16(float* d, const uint32_t* a, uint32_t b0, uint32_t b1) {
    asm volatile(
        "mma.sync.aligned.m16n8k16.row.col.f32.bf16.bf16.f32 "
        "{%0,%1,%2,%3}, {%4,%5,%6,%7}, {%8,%9}, {%0,%1,%2,%3};"
        : "+f"(d[0]), "+f"(d[1]), "+f"(d[2]), "+f"(d[3])
        : "r"(a[0]), "r"(a[1]), "r"(a[2]), "r"(a[3]), "r"(b0), "r"(b1));
}
__device__ __forceinline__ void split2(float v0, float v1,
                                       __nv_bfloat162* hi, __nv_bfloat162* lo) {
    __nv_bfloat162 h, l;
    h.x = __float2bfloat16(v0);
    h.y = __float2bfloat16(v1);
    l.x = __float2bfloat16(v0 - __bfloat162float(h.x));
    l.y = __float2bfloat16(v1 - __bfloat162float(h.y));
    *hi = h; *lo = l;
}

// ---------------------------------------------------------------------------
// Prep: all weights in ONE kernel.
// conv: w[o][i][k] -> [(tap*256+o)*256 + i];  proj: Wl[k][o] -> [o*1024+k]
// ---------------------------------------------------------------------------
__global__ void wprep_all_kernel(const float* __restrict__ w0,
                                 const float* __restrict__ w1,
                                 const float* __restrict__ w2,
                                 const float* __restrict__ wl,
                                 __nv_bfloat16* __restrict__ wkh,
                                 __nv_bfloat16* __restrict__ wkl,
                                 __nv_bfloat16* __restrict__ wlh,
                                 __nv_bfloat16* __restrict__ wll) {
    const int bid = blockIdx.x;
    if (bid < 2304) {
        const int layer = bid / 768, blk = bid - layer * 768;
        const float* w = (layer == 0) ? w0 : (layer == 1) ? w1 : w2;
        const int idx = blk * 256 + threadIdx.x;            // 0..196607
        const int o = idx / (Cn * 3);
        const int rem = idx - o * (Cn * 3);
        const int i = rem / 3, k = rem - i * 3;
        const float v = w[idx];
        const __nv_bfloat16 h = __float2bfloat16(v);
        const size_t d = (size_t)layer * 3 * Cn * Cn + ((size_t)k * Cn + o) * Cn + i;
        wkh[d] = h;
        wkl[d] = __float2bfloat16(v - __bfloat162float(h));
    } else {
        const int idx = (bid - 2304) * 256 + threadIdx.x;   // 0..262143
        const int o = idx >> 10, k = idx & 1023;
        const float v = wl[(size_t)k * Cn + o];
        const __nv_bfloat16 h = __float2bfloat16(v);
        wlh[idx] = h;
        wll[idx] = __float2bfloat16(v - __bfloat162float(h));
    }
}
__global__ void esplit_kernel(const float4* __restrict__ E,
                              __nv_bfloat162* __restrict__ hi,
                              __nv_bfloat162* __restrict__ lo) {
    size_t idx = (size_t)blockIdx.x * 256 + threadIdx.x;
    float4 v = E[idx];
    split2(v.x, v.y, &hi[idx * 2], &lo[idx * 2]);
    split2(v.z, v.w, &hi[idx * 2 + 1], &lo[idx * 2 + 1]);
}

// ---------------------------------------------------------------------------
// bf16x3 mma GEMM/conv on [L,B,C]. M128 x N256 per CTA, 512 threads, 16 warps
// (wm=(wid&3)*32, wn=(wid>>2)*64). 3-stage cp.async pipeline, 2 groups in
// flight. MMA inner loop runs 3 sweeps (hh, hl, lh) over ALL 16 accumulators
// so accumulator reuse distance (32 MMAs) far exceeds HMMA latency.
// Per-acc addition order (hh, hl, lh within each ks) is unchanged -> bitwise
// identical results to the previous interleaving.
// ---------------------------------------------------------------------------
template <bool PROJ, int DIL, bool RELU, bool SPLIT>
__global__ void __launch_bounds__(512, 1) mma_kernel(
    const __nv_bfloat16* __restrict__ Xhi, const __nv_bfloat16* __restrict__ Xlo,
    const __nv_bfloat16* __restrict__ Whi, const __nv_bfloat16* __restrict__ Wlo,
    const float* __restrict__ bias,
    __nv_bfloat16* __restrict__ Yhi, __nv_bfloat16* __restrict__ Ylo,
    float* __restrict__ Yf) {
    constexpr int NCH = PROJ ? 32 : 24;

    extern __shared__ __align__(16) char smem[];
    const int tid = threadIdx.x, wid = tid >> 5, lane = tid & 31;
    const int r4 = lane >> 2, c4 = lane & 3;
    const int wm = (wid & 3) * 32, wn = (wid >> 2) * 64;
    const uint32_t smem_u = s2u(smem);

    // ldmatrix per-lane address components
    const int lane15 = lane & 15;
    const uint32_t a_off = ((lane >> 4) & 1) << 4;
    const int b_rowl = (lane & 7) + ((lane >> 4) & 1) * 8;
    const uint32_t b_off = ((lane >> 3) & 1) << 4;

    const int tile = blockIdx.x;           // proj: m-tile; conv: l index
    const int m0 = tile * 128;

    float acc[2][8][4];
#pragma unroll
    for (int mt = 0; mt < 2; mt++)
#pragma unroll
        for (int nt = 0; nt < 8; nt++)
#pragma unroll
            for (int j = 0; j < 4; j++) acc[mt][nt][j] = 0.f;

    auto load_chunk = [&](int c) {
        const uint32_t sb = smem_u + (c % NSTG) * STAGE;
        const int tap = PROJ ? 0 : (c >> 3);
        const int kc = PROJ ? c : (c & 7);
        const int lsrc = PROJ ? 0 : (tile + (tap - 1) * DIL);
        const bool avalid = PROJ || ((unsigned)lsrc < (unsigned)Ln);
#pragma unroll
        for (int q = 0; q < 2; q++) {                       // A: 1024 ops
            const int idx = q * 512 + tid;
            const int plane = idx >> 9, row = (idx >> 2) & 127, cg = idx & 3;
            const uint32_t dst = sb + plane * PLA + row * RSTR + cg * 16;
            const __nv_bfloat16* P = plane ? Xlo : Xhi;
            if (PROJ)
                cpa16(dst, P + (size_t)(m0 + row) * Dn + kc * 32 + cg * 8);
            else if (avalid)
                cpa16(dst, P + ((size_t)lsrc * Bn + row) * Cn + kc * 32 + cg * 8);
            else
                zfill16(dst);
        }
#pragma unroll
        for (int q = 0; q < 4; q++) {                       // B: 2048 ops (256 rows)
            const int idx = q * 512 + tid;
            const int plane = idx >> 10, row = (idx >> 2) & 255, cg = idx & 3;
            const uint32_t dst = sb + 2 * PLA + plane * PLB + row * RSTR + cg * 16;
            const __nv_bfloat16* P = plane ? Wlo : Whi;
            if (PROJ)
                cpa16(dst, P + (size_t)row * Dn + kc * 32 + cg * 8);
            else
                cpa16(dst, P + ((size_t)tap * Cn + row) * Cn + kc * 32 + cg * 8);
        }
        cpa_commit();
    };

    load_chunk(0);
    load_chunk(1);
    for (int c = 0; c < NCH; c++) {
        cpa_wait<1>();          // stage c resident (c+1 may still be in flight)
        __syncthreads();        // all threads past compute(c-1): stage (c+2)%3 free
        if (c + 2 < NCH) load_chunk(c + 2);

        const uint32_t sb = smem_u + (c % NSTG) * STAGE;
        const uint32_t ab = sb + (wm + lane15) * RSTR + a_off;
        const uint32_t bbs = sb + 2 * PLA + (wn + b_rowl) * RSTR + b_off;
#pragma unroll
        for (int ks = 0; ks < 2; ks++) {
            uint32_t ah[2][4], al[2][4];
            ldsm4(ah[0], ab + ks * 32);
            ldsm4(ah[1], ab + 16 * RSTR + ks * 32);
            ldsm4(al[0], ab + PLA + ks * 32);
            ldsm4(al[1], ab + PLA + 16 * RSTR + ks * 32);
            uint32_t bh[4][4], blr[4][4];
#pragma unroll
            for (int p = 0; p < 4; p++) {
                ldsm4(bh[p],  bbs + p * 16 * RSTR + ks * 32);
                ldsm4(blr[p], bbs + PLB + p * 16 * RSTR + ks * 32);
            }
            // Sweep 1: Ahi x Bhi over all 16 accumulators
#pragma unroll
            for (int p = 0; p < 4; p++)
#pragma unroll
                for (int h = 0; h < 2; h++) {
                    const int nt = 2 * p + h;
                    mma16(acc[0][nt], ah[0], bh[p][2 * h], bh[p][2 * h + 1]);
                    mma16(acc[1][nt], ah[1], bh[p][2 * h], bh[p][2 * h + 1]);
                }
            // Sweep 2: Ahi x Blo
#pragma unroll
            for (int p = 0; p < 4; p++)
#pragma unroll
                for (int h = 0; h < 2; h++) {
                    const int nt = 2 * p + h;
                    mma16(acc[0][nt], ah[0], blr[p][2 * h], blr[p][2 * h + 1]);
                    mma16(acc[1][nt], ah[1], blr[p][2 * h], blr[p][2 * h + 1]);
                }
            // Sweep 3: Alo x Bhi
#pragma unroll
            for (int p = 0; p < 4; p++)
#pragma unroll
                for (int h = 0; h < 2; h++) {
                    const int nt = 2 * p + h;
                    mma16(acc[0][nt], al[0], bh[p][2 * h], bh[p][2 * h + 1]);
                    mma16(acc[1][nt], al[1], bh[p][2 * h], bh[p][2 * h + 1]);
                }
        }
    }

    // ---- epilogue: bias (+ReLU); split-store to [L,B,C] or fp32 [B,L,C] ----
#pragma unroll
    for (int mt = 0; mt < 2; mt++) {
        const int rowl = wm + mt * 16 + r4;    // local m row (conv: batch b)
#pragma unroll
        for (int half = 0; half < 2; half++) {
            const int rl = rowl + half * 8;
            size_t yrow;
            if (PROJ) {
                const int m = m0 + rl;
                const int b = m / Ln, l = m - b * Ln;
                yrow = (size_t)l * Bn + b;
            } else if (SPLIT) {
                yrow = (size_t)tile * Bn + rl;           // [L,B,C]
            } else {
                yrow = (size_t)rl * Ln + tile;           // fp32 out [B,L,C]
            }
#pragma unroll
            for (int nt = 0; nt < 8; nt++) {
                const int col = wn + nt * 8 + c4 * 2;
                const float bz0 = __ldg(bias + col);
                const float bz1 = __ldg(bias + col + 1);
                float v0 = acc[mt][nt][2 * half]     + bz0;
                float v1 = acc[mt][nt][2 * half + 1] + bz1;
                if (RELU) { v0 = fmaxf(v0, 0.f); v1 = fmaxf(v1, 0.f); }
                if (SPLIT) {
                    split2(v0, v1,
                           (__nv_bfloat162*)(Yhi + yrow * Cn + col),
                           (__nv_bfloat162*)(Ylo + yrow * Cn + col));
                } else {
                    *(float2*)(Yf + yrow * Cn + col) = make_float2(v0, v1);
                }
            }
        }
    }
}

// ---------------------------------------------------------------------------
// LayerNorm over L per (b,c) on split [L,B,C] planes, 2-pass, strip-parallel.
// Block 256 thr = 64 channels x 4 L-strips. Grid (Bn, 4).
// torch-style: unbiased var (ddof=1), divide by (std + eps).
// ---------------------------------------------------------------------------
template <bool RELU>
__global__ __launch_bounds__(256) void ln_kernel(
    __nv_bfloat16* __restrict__ hi, __nv_bfloat16* __restrict__ lo,
    const float* __restrict__ g, const float* __restrict__ be) {
    __shared__ float red[2][4][64];
    __shared__ float stat[2][64];
    const int b = blockIdx.x, cg = blockIdx.y;
    const int cl = threadIdx.x & 63, strip = threadIdx.x >> 6;
    const size_t base = (size_t)b * Cn + cg * 64 + cl;

    float s = 0.f, q = 0.f;
    for (int l = strip; l < Ln; l += 4) {
        const size_t off = base + (size_t)l * Bn * Cn;
        float x = __bfloat162float(hi[off]) + __bfloat162float(lo[off]);
        if (RELU) x = fmaxf(x, 0.f);
        s += x; q += x * x;
    }
    red[0][strip][cl] = s;
    red[1][strip][cl] = q;
    __syncthreads();
    if (threadIdx.x < 64) {
        float st = red[0][0][cl] + red[0][1][cl] + red[0][2][cl] + red[0][3][cl];
        float qt = red[1][0][cl] + red[1][1][cl] + red[1][2][cl] + red[1][3][cl];
        const float mean = st * (1.f / Ln);
        const float var = fmaxf((qt - st * mean) * (1.f / (Ln - 1)), 0.f);
        stat[0][cl] = mean;
        stat[1][cl] = 1.f / (sqrtf(var) + 1e-6f);
    }
    __syncthreads();
    const float mean = stat[0][cl], inv = stat[1][cl];
    for (int l = strip; l < Ln; l += 4) {
        const size_t off = base + (size_t)l * Bn * Cn;
        float x = __bfloat162float(hi[off]) + __bfloat162float(lo[off]);
        if (RELU) x = fmaxf(x, 0.f);
        const float y = g[l] * ((x - mean) * inv) + be[l];
        const __nv_bfloat16 h = __float2bfloat16(y);
        hi[off] = h;
        lo[off] = __float2bfloat16(y - __bfloat162float(h));
    }
}

// ---------------------------------------------------------------------------
// Host orchestration
// ---------------------------------------------------------------------------
extern "C" void kernel_launch(void* const* d_in, const int* in_sizes, int n_in,
                              void* d_out, int out_size) {
    const float* E   = (const float*)d_in[0];
    const float* Wl  = (const float*)d_in[2];
    const float* bl  = (const float*)d_in[3];
    const float* w0  = (const float*)d_in[4];
    const float* b0  = (const float*)d_in[5];
    const float* w1  = (const float*)d_in[6];
    const float* b1  = (const float*)d_in[7];
    const float* w2  = (const float*)d_in[8];
    const float* b2  = (const float*)d_in[9];
    const float* g1  = (const float*)d_in[10];
    const float* be1 = (const float*)d_in[11];
    const float* g2  = (const float*)d_in[12];
    const float* be2 = (const float*)d_in[13];
    float* out = (float*)d_out;

    __nv_bfloat16 *Ah, *Al, *Bh, *Bl, *Eh, *El, *wkh, *wkl, *wlh, *wll;
    cudaGetSymbolAddress((void**)&Ah, g_Ahi);
    cudaGetSymbolAddress((void**)&Al, g_Alo);
    cudaGetSymbolAddress((void**)&Bh, g_Bhi);
    cudaGetSymbolAddress((void**)&Bl, g_Blo);
    cudaGetSymbolAddress((void**)&Eh, g_Ehi);
    cudaGetSymbolAddress((void**)&El, g_Elo);
    cudaGetSymbolAddress((void**)&wkh, g_wkhi);
    cudaGetSymbolAddress((void**)&wkl, g_wklo);
    cudaGetSymbolAddress((void**)&wlh, g_wlhi);
    cudaGetSymbolAddress((void**)&wll, g_wllo);
    __nv_bfloat16* wk0h = wkh;               __nv_bfloat16* wk0l = wkl;
    __nv_bfloat16* wk1h = wkh + 3 * Cn * Cn; __nv_bfloat16* wk1l = wkl + 3 * Cn * Cn;
    __nv_bfloat16* wk2h = wkh + 6 * Cn * Cn; __nv_bfloat16* wk2l = wkl + 6 * Cn * Cn;

    cudaFuncSetAttribute(mma_kernel<true, 1, false, true>,
                         cudaFuncAttributeMaxDynamicSharedMemorySize, SMEM_TOT);
    cudaFuncSetAttribute(mma_kernel<false, 1, true, true>,
                         cudaFuncAttributeMaxDynamicSharedMemorySize, SMEM_TOT);
    cudaFuncSetAttribute(mma_kernel<false, 1, false, true>,
                         cudaFuncAttributeMaxDynamicSharedMemorySize, SMEM_TOT);
    cudaFuncSetAttribute(mma_kernel<false, 2, false, true>,
                         cudaFuncAttributeMaxDynamicSharedMemorySize, SMEM_TOT);
    cudaFuncSetAttribute(mma_kernel<false, 2, false, false>,
                         cudaFuncAttributeMaxDynamicSharedMemorySize, SMEM_TOT);

    wprep_all_kernel<<<3328, 256>>>(w0, w1, w2, Wl, wkh, wkl, wlh, wll);
    esplit_kernel<<<51200, 256>>>((const float4*)E, (__nv_bfloat162*)Eh,
                                  (__nv_bfloat162*)El);

    // projection: [51200,1024] x [1024,256] -> A planes [L,B,C]
    mma_kernel<true, 1, false, true><<<400, 512, SMEM_TOT>>>(
        Eh, El, wlh, wll, bl, Ah, Al, nullptr);

    const int CG = Ln;              // 400 l-tiles, full N per CTA
    const dim3 LG(Bn, 4);

    // net 1: A -> B
    mma_kernel<false, 1, true,  true><<<CG, 512, SMEM_TOT>>>(Ah, Al, wk0h, wk0l, b0, Bh, Bl, nullptr);
    ln_kernel<false><<<LG, 256>>>(Bh, Bl, g1, be1);
    mma_kernel<false, 1, false, true><<<CG, 512, SMEM_TOT>>>(Bh, Bl, wk1h, wk1l, b1, Ah, Al, nullptr);
    mma_kernel<false, 2, false, true><<<CG, 512, SMEM_TOT>>>(Ah, Al, wk2h, wk2l, b2, Bh, Bl, nullptr);

    ln_kernel<true><<<LG, 256>>>(Bh, Bl, g2, be2);   // ReLU + outer LN

    // net 2: B -> A
    mma_kernel<false, 1, true,  true><<<CG, 512, SMEM_TOT>>>(Bh, Bl, wk0h, wk0l, b0, Ah, Al, nullptr);
    ln_kernel<false><<<LG, 256>>>(Ah, Al, g1, be1);
    mma_kernel<false, 1, false, true><<<CG, 512, SMEM_TOT>>>(Ah, Al, wk1h, wk1l, b1, Bh, Bl, nullptr);
    mma_kernel<false, 2, false, true><<<CG, 512, SMEM_TOT>>>(Bh, Bl, wk2h, wk2l, b2, Ah, Al, nullptr);

    // net 3: A -> B
    mma_kernel<false, 1, true,  true><<<CG, 512, SMEM_TOT>>>(Ah, Al, wk0h, wk0l, b0, Bh, Bl, nullptr);
    ln_kernel<false><<<LG, 256>>>(Bh, Bl, g1, be1);
    mma_kernel<false, 1, false, true><<<CG, 512, SMEM_TOT>>>(Bh, Bl, wk1h, wk1l, b1, Ah, Al, nullptr);
    mma_kernel<false, 2, false, true><<<CG, 512, SMEM_TOT>>>(Ah, Al, wk2h, wk2l, b2, Bh, Bl, nullptr);

    // net 4: B -> out (final conv writes fp32 d_out [B,L,C])
    mma_kernel<false, 1, true,  true><<<CG, 512, SMEM_TOT>>>(Bh, Bl, wk0h, wk0l, b0, Ah, Al, nullptr);
    ln_kernel<false><<<LG, 256>>>(Ah, Al, g1, be1);
    mma_kernel<false, 1, false, true><<<CG, 512, SMEM_TOT>>>(Ah, Al, wk1h, wk1l, b1, Bh, Bl, nullptr);
    mma_kernel<false, 2, false, false><<<CG, 512, SMEM_TOT>>>(Bh, Bl, wk2h, wk2l, b2, nullptr, nullptr, out);
}